// round 6
// baseline (speedup 1.0000x reference)
#include <cuda_runtime.h>
#include <cuda_bf16.h>
#include <limits.h>

#define N_IMG 256
#define IMG_F4 65536                     // float4 per image (512x512 / 4)
#define UNITS_PER_IMG 512                // one unit = 128 f4 = one image row
#define N_UNITS (N_IMG * UNITS_PER_IMG)  // 131072
#define THREADS 256
#define WARPS_PER_BLOCK 8
#define GRID_BLOCKS 888                  // 148 SM x 6
#define N_WARPS (GRID_BLOCKS * WARPS_PER_BLOCK)  // 7104
#define THRESH 0x3F000000u               // bits of 0.5f; f>=0.5 <=> bits>=THRESH (f>=0)

// Per-image accumulators. All use atomicMax with neutral element 0:
//   xmax, ymax directly; the global "all pixels set" min is stored as ~min.
// Static zero-init == neutral; last block resets them -> graph-replay safe.
__device__ int g_xmax[N_IMG];
__device__ int g_ymax[N_IMG];
__device__ unsigned int g_nmax[N_IMG];   // ~(unsigned min of all pixel bits)
__device__ unsigned int g_done = 0;

__device__ __forceinline__ uint4 umax4(uint4 a, uint4 b) {
    return make_uint4(max(a.x, b.x), max(a.y, b.y), max(a.z, b.z), max(a.w, b.w));
}
__device__ __forceinline__ uint4 umin4(uint4 a, uint4 b) {
    return make_uint4(min(a.x, b.x), min(a.y, b.y), min(a.z, b.z), min(a.w, b.w));
}

// Flush one image's per-warp partial state to global accumulators.
__device__ __forceinline__ void flush_img(int img, int lane,
                                          const uint4 cmax[4], int ylast,
                                          uint4 nacc) {
    // Decode xmax from per-lane column maxes. Lane covers f4-columns
    // lane, lane+32, lane+64, lane+96; element e is pixel col 4*c+e (+1).
    int xmax = 0;
#pragma unroll
    for (int s = 0; s < 4; s++) {
        const uint4 c = cmax[s];
        const int base = (lane + 32 * s) << 2;
        int v = 0;
        if (c.x >= THRESH) v = base + 1;
        if (c.y >= THRESH) v = base + 2;
        if (c.z >= THRESH) v = base + 3;
        if (c.w >= THRESH) v = base + 4;
        xmax = max(xmax, v);
    }
    unsigned nmin = min(min(nacc.x, nacc.y), min(nacc.z, nacc.w));

    xmax = __reduce_max_sync(0xFFFFFFFFu, xmax);
    const int ymax = __reduce_max_sync(0xFFFFFFFFu, ylast);
    nmin = __reduce_min_sync(0xFFFFFFFFu, nmin);

    if (lane == 0)      atomicMax(&g_xmax[img], xmax);
    else if (lane == 1) atomicMax(&g_ymax[img], ymax);
    else if (lane == 2) atomicMax(&g_nmax[img], ~nmin);
}

__global__ __launch_bounds__(THREADS) void bb_kernel(
    const float* __restrict__ mask, float* __restrict__ out) {
    const int tid  = threadIdx.x;
    const int wid  = tid >> 5;
    const int lane = tid & 31;

    // Balanced warp ranges over 131072 row-units (each warp: 18 or 19 units,
    // remainder interleaved across warps/SMs).
    const int gw = blockIdx.x * WARPS_PER_BLOCK + wid;
    unsigned u    = (unsigned)(((unsigned long long)gw       * N_UNITS) / N_WARPS);
    const unsigned uend = (unsigned)(((unsigned long long)(gw + 1) * N_UNITS) / N_WARPS);

    const uint4* __restrict__ mf4 = reinterpret_cast<const uint4*>(mask);

    int cur_img = (int)(u >> 9);          // 512 units per image
    uint4 cmax[4] = {make_uint4(0,0,0,0), make_uint4(0,0,0,0),
                     make_uint4(0,0,0,0), make_uint4(0,0,0,0)};
    uint4 nacc = make_uint4(~0u, ~0u, ~0u, ~0u);
    int ylast = 0;

    for (; u < uend; ++u) {
        const int img = (int)(u >> 9);
        if (img != cur_img) {
            flush_img(cur_img, lane, cmax, ylast, nacc);
            cmax[0] = cmax[1] = cmax[2] = cmax[3] = make_uint4(0,0,0,0);
            nacc = make_uint4(~0u, ~0u, ~0u, ~0u);
            ylast = 0;
            cur_img = img;
        }

        const size_t base = (size_t)u * 128 + lane;
        const uint4 a = mf4[base];
        const uint4 b = mf4[base + 32];
        const uint4 c = mf4[base + 64];
        const uint4 d = mf4[base + 96];

        // Column occupancy (position encoded by slot/element, decoded at flush)
        cmax[0] = umax4(cmax[0], a);
        cmax[1] = umax4(cmax[1], b);
        cmax[2] = umax4(cmax[2], c);
        cmax[3] = umax4(cmax[3], d);

        // Global min (for the "all pixels set" xmin/ymin case)
        nacc = umin4(nacc, umin4(umin4(a, b), umin4(c, d)));

        // Row occupancy: rows ascend within the range, so ymax = last dirty row
        const uint4 mx = umax4(umax4(a, b), umax4(c, d));
        const unsigned m = max(max(mx.x, mx.y), max(mx.z, mx.w));
        ylast = (m >= THRESH) ? (int)(u & 511) + 1 : ylast;
    }
    flush_img(cur_img, lane, cmax, ylast, nacc);

    // Single end-of-kernel sync: done ticket, last block writes outputs.
    __shared__ bool s_last;
    __syncthreads();
    if (tid == 0) {
        __threadfence();
        s_last = (atomicAdd(&g_done, 1u) == GRID_BLOCKS - 1);
    }
    __syncthreads();
    if (!s_last) return;

    {
        const int i = tid;                 // one image per thread
        const int   xmax = g_xmax[i];
        const int   ymax = g_ymax[i];
        const unsigned nmin = ~g_nmax[i];
        const int   mnv  = (nmin >= THRESH) ? 1 : 0;   // all-set => mins are 1

        const float xminf = (float)mnv;
        const float yminf = (float)mnv;
        const float xmaxf = (float)xmax;
        const float ymaxf = (float)ymax;

        // Layout: [0,256) object_found | [256,1280) bbox_scaled | [1280,2304) bbox*2
        out[i] = ((ymaxf > yminf) && (xmaxf > xminf)) ? 1.0f : 0.0f;

        float* bb = out + 256 + i * 4;
        bb[0] = xminf; bb[1] = yminf; bb[2] = xmaxf; bb[3] = ymaxf;

        float* bb2 = out + 1280 + i * 4;
        bb2[0] = xminf * 2.0f; bb2[1] = yminf * 2.0f;
        bb2[2] = xmaxf * 2.0f; bb2[3] = ymaxf * 2.0f;

        // Reset accumulators + ticket for the next graph replay.
        g_xmax[i] = 0; g_ymax[i] = 0; g_nmax[i] = 0u;
        if (tid == 0) g_done = 0u;
    }
}

extern "C" void kernel_launch(void* const* d_in, const int* in_sizes, int n_in,
                              void* d_out, int out_size) {
    const float* mask = (const float*)d_in[0];
    float* out = (float*)d_out;
    bb_kernel<<<GRID_BLOCKS, THREADS>>>(mask, out);
}